// round 3
// baseline (speedup 1.0000x reference)
#include <cuda_runtime.h>
#include <cuda_bf16.h>
#include <cstdint>
#include <math.h>

#define N_IN   8192
#define N_MC   32768
#define K_TOP  656
#define MASK_WORDS (N_IN / 32)          // 256

__device__ float g_overlap[N_MC];

// ---------------------------------------------------------------------------
// Kernel 1 (fused): per-block mask build + overlap
//   overlap_eff[row] = exp(na-dc) * popcount((perm_row >= 0.5) & I)
// One warp per row; float4 streaming of the 1.07 GB matrix with .cs hint.
// ---------------------------------------------------------------------------
__global__ __launch_bounds__(256) void overlap_kernel(
    const float* __restrict__ I,
    const float* __restrict__ perm,
    const float* __restrict__ duty,
    const float* __restrict__ navg)
{
    __shared__ uint32_t smask[MASK_WORDS];
    const int t    = threadIdx.x;
    const int warp = t >> 5;
    const int lane = t & 31;

    // build input bitmask from I (float 0.0/1.0); I is L2-resident (32 KB)
    #pragma unroll
    for (int k2 = 0; k2 < 32; ++k2) {
        float v = I[k2 * 256 + t];
        unsigned ball = __ballot_sync(0xffffffffu, v != 0.0f);
        if (lane == 0) smask[k2 * 8 + warp] = ball;
    }
    __syncthreads();

    const int row = blockIdx.x * 8 + warp;
    const float4* p = reinterpret_cast<const float4*>(perm + (size_t)row * N_IN);

    int cnt = 0;
    // 2048 float4 per row; 64 per lane
    #pragma unroll 8
    for (int it = 0; it < 64; ++it) {
        int c4 = it * 32 + lane;
        float4 v = __ldcs(&p[c4]);               // streaming, evict-first
        int c = c4 * 4;
        uint32_t m = smask[c >> 5] >> (c & 31);
        cnt += ((m & 1u) && v.x >= 0.5f);
        cnt += ((m & 2u) && v.y >= 0.5f);
        cnt += ((m & 4u) && v.z >= 0.5f);
        cnt += ((m & 8u) && v.w >= 0.5f);
    }
    cnt = __reduce_add_sync(0xffffffffu, cnt);

    if (lane == 0) {
        float d = navg[row] - duty[row];
        float boost = (float)exp((double)d);     // correctly-rounded f32 exp
        g_overlap[row] = boost * (float)cnt;
    }
}

// ---------------------------------------------------------------------------
// Kernel 2: exact top-K (K=656), jax.lax.top_k tie semantics
// (threshold ties resolved lowest-index-first).
// Single block, 1024 threads. Keys staged in 128 KB dynamic shared.
// 4 x 8-bit radix-select with warp-aggregated histogram atomics and
// parallel suffix-scan bin selection; then a 2-barrier marking pass.
// ---------------------------------------------------------------------------
extern __shared__ uint32_t skeys[];   // N_MC u32 = 131072 bytes

__global__ __launch_bounds__(1024) void topk_kernel(float* __restrict__ out)
{
    __shared__ uint32_t s_hist[256];
    __shared__ uint32_t s_scan[256];    // inclusive suffix sums (by tid order)
    __shared__ uint32_t s_wtot[32];
    __shared__ uint32_t s_prefix;
    __shared__ int      s_rem;

    const int tid  = threadIdx.x;
    const int lane = tid & 31;
    const int wid  = tid >> 5;

    // stage keys (all overlaps >= 0, so u32 bit order == float order)
    for (int j = tid; j < N_MC; j += 1024)
        skeys[j] = __float_as_uint(g_overlap[j]);

    if (tid == 0) { s_prefix = 0u; s_rem = K_TOP; }
    __syncthreads();

    // ---- radix select: find T = K-th largest key ----
    for (int shift = 24; shift >= 0; shift -= 8) {
        if (tid < 256) s_hist[tid] = 0u;
        __syncthreads();
        const uint32_t prefix = s_prefix;

        for (int j = tid; j < N_MC; j += 1024) {
            uint32_t k = skeys[j];
            uint32_t diff = k ^ prefix;
            bool cand = (shift == 24) || ((diff >> (shift + 8)) == 0u);
            unsigned amask = __ballot_sync(0xffffffffu, cand);
            if (cand) {
                uint32_t bin = (k >> shift) & 255u;
                unsigned peers = __match_any_sync(amask, bin);
                if (lane == (__ffs(peers) - 1))
                    atomicAdd(&s_hist[bin], (uint32_t)__popc(peers));
            }
        }
        __syncthreads();

        // parallel suffix sums: s = hist[255-tid]; inclusive scan over tid
        if (tid < 256) {
            uint32_t v = s_hist[255 - tid];
            #pragma unroll
            for (int off = 1; off < 32; off <<= 1) {
                uint32_t u = __shfl_up_sync(0xffffffffu, v, off);
                if (lane >= off) v += u;
            }
            if (lane == 31) s_wtot[wid] = v;
            s_scan[tid] = v;
        }
        __syncthreads();
        if (tid < 256) {
            uint32_t add = 0;
            #pragma unroll
            for (int w = 0; w < 8; ++w) add += (wid > w) ? s_wtot[w] : 0u;
            uint32_t inc = s_scan[tid] + add;
            s_scan[tid] = inc;
        }
        __syncthreads();
        if (tid < 256) {
            int rem = s_rem;
            uint32_t inc = s_scan[tid];
            uint32_t prev = (tid == 0) ? 0u : s_scan[tid - 1];
            if ((int)inc >= rem && (int)prev < rem) {   // unique tid
                int b = 255 - tid;
                s_prefix = prefix | ((uint32_t)b << shift);
                s_rem = rem - (int)prev;
            }
        }
        __syncthreads();
    }

    const uint32_t T = s_prefix;   // exact K-th largest key
    const int      r = s_rem;      // # of ==T entries to keep (lowest index)

    // ---- marking pass: contiguous 32-key chunk per thread, 1 block scan ----
    const int base = tid * 32;
    int c = 0;
    #pragma unroll 4
    for (int i = 0; i < 32; ++i)
        c += (skeys[base + i] == T);

    // exclusive block scan of c (index order == tid order)
    int v = c;
    #pragma unroll
    for (int off = 1; off < 32; off <<= 1) {
        int u = __shfl_up_sync(0xffffffffu, v, off);
        if (lane >= off) v += u;
    }
    if (lane == 31) s_wtot[wid] = (uint32_t)v;
    __syncthreads();
    if (wid == 0) {
        int wv = (int)s_wtot[lane];
        #pragma unroll
        for (int off = 1; off < 32; off <<= 1) {
            int u = __shfl_up_sync(0xffffffffu, wv, off);
            if (lane >= off) wv += u;
        }
        s_wtot[lane] = (uint32_t)wv;   // inclusive scan of warp totals
    }
    __syncthreads();

    int excl = v - c + ((wid == 0) ? 0 : (int)s_wtot[wid - 1]);

    int rank = excl;
    #pragma unroll 4
    for (int i = 0; i < 32; ++i) {
        uint32_t k = skeys[base + i];
        bool eq = (k == T);
        bool gt = (k > T);
        out[base + i] = (gt || (eq && rank < r)) ? 1.0f : 0.0f;
        rank += eq;
    }
}

// ---------------------------------------------------------------------------
extern "C" void kernel_launch(void* const* d_in, const int* in_sizes, int n_in,
                              void* d_out, int out_size)
{
    const float* I    = (const float*)d_in[0];
    const float* perm = (const float*)d_in[1];
    const float* duty = (const float*)d_in[2];
    const float* navg = (const float*)d_in[3];
    float* out = (float*)d_out;

    (void)in_sizes; (void)n_in; (void)out_size;

    cudaFuncSetAttribute(topk_kernel,
                         cudaFuncAttributeMaxDynamicSharedMemorySize,
                         N_MC * (int)sizeof(uint32_t));

    overlap_kernel<<<N_MC / 8, 256>>>(I, perm, duty, navg);
    topk_kernel<<<1, 1024, N_MC * sizeof(uint32_t)>>>(out);
}

// round 4
// speedup vs baseline: 1.1143x; 1.1143x over previous
#include <cuda_runtime.h>
#include <cuda_bf16.h>
#include <cstdint>
#include <math.h>

#define N_IN   8192
#define N_MC   32768
#define K_TOP  656
#define MASK_WORDS (N_IN / 32)          // 256

__device__ float g_overlap[N_MC];

// ---------------------------------------------------------------------------
// Kernel 1 (fused): per-block mask build + overlap
//   overlap_eff[row] = exp(na-dc) * popcount((perm_row >= 0.5) & I)
// 1024 threads/block, one warp per row (32 rows/block), float4 .cs streaming.
// ---------------------------------------------------------------------------
__global__ __launch_bounds__(1024) void overlap_kernel(
    const float* __restrict__ I,
    const float* __restrict__ perm,
    const float* __restrict__ duty,
    const float* __restrict__ navg)
{
    __shared__ uint32_t smask[MASK_WORDS];
    const int t    = threadIdx.x;
    const int warp = t >> 5;
    const int lane = t & 31;

    // build input bitmask from I (float 0.0/1.0); I is L2-resident (32 KB)
    #pragma unroll
    for (int k2 = 0; k2 < 8; ++k2) {
        float v = I[k2 * 1024 + t];
        unsigned ball = __ballot_sync(0xffffffffu, v != 0.0f);
        if (lane == 0) smask[k2 * 32 + warp] = ball;
    }
    __syncthreads();

    const int row = blockIdx.x * 32 + warp;
    const float4* p = reinterpret_cast<const float4*>(perm + (size_t)row * N_IN);

    int cnt = 0;
    // 2048 float4 per row; 64 per lane
    #pragma unroll 8
    for (int it = 0; it < 64; ++it) {
        int c4 = it * 32 + lane;
        float4 v = __ldcs(&p[c4]);               // streaming, evict-first
        int c = c4 * 4;
        uint32_t m = smask[c >> 5] >> (c & 31);
        cnt += ((m & 1u) && v.x >= 0.5f);
        cnt += ((m & 2u) && v.y >= 0.5f);
        cnt += ((m & 4u) && v.z >= 0.5f);
        cnt += ((m & 8u) && v.w >= 0.5f);
    }
    cnt = __reduce_add_sync(0xffffffffu, cnt);

    if (lane == 0) {
        float d = navg[row] - duty[row];
        float boost = (float)exp((double)d);     // correctly-rounded f32 exp
        g_overlap[row] = boost * (float)cnt;
    }
}

// ---------------------------------------------------------------------------
// Kernel 2: exact top-K (K=656), jax.lax.top_k tie semantics
// (threshold ties resolved lowest-index-first).
// Single block, 1024 threads, keys in 128 KB dynamic shared.
// 4 x 8-bit radix-select (warp-aggregated histogram atomics, parallel
// suffix-scan bin pick), then a CONFLICT-FREE 2-phase marking pass:
// each warp owns a contiguous 1024-key segment, lanes read consecutive
// addresses, ranks tracked via ballot/popc in registers.
// ---------------------------------------------------------------------------
extern __shared__ uint32_t skeys[];   // N_MC u32 = 131072 bytes

__global__ __launch_bounds__(1024) void topk_kernel(float* __restrict__ out)
{
    __shared__ uint32_t s_hist[256];
    __shared__ uint32_t s_scan[256];
    __shared__ uint32_t s_wtot[32];
    __shared__ uint32_t s_prefix;
    __shared__ int      s_rem;

    const int tid  = threadIdx.x;
    const int lane = tid & 31;
    const int wid  = tid >> 5;

    // stage keys (all overlaps >= 0, so u32 bit order == float order)
    for (int j = tid; j < N_MC; j += 1024)
        skeys[j] = __float_as_uint(g_overlap[j]);

    if (tid == 0) { s_prefix = 0u; s_rem = K_TOP; }
    __syncthreads();

    // ---- radix select: find T = K-th largest key ----
    #pragma unroll
    for (int shift = 24; shift >= 0; shift -= 8) {
        if (tid < 256) s_hist[tid] = 0u;
        __syncthreads();
        const uint32_t prefix = s_prefix;

        for (int j = tid; j < N_MC; j += 1024) {   // coalesced, conflict-free
            uint32_t k = skeys[j];
            bool cand = (shift == 24) || (((k ^ prefix) >> (shift + 8)) == 0u);
            unsigned amask = __ballot_sync(0xffffffffu, cand);
            if (cand) {
                uint32_t bin = (k >> shift) & 255u;
                unsigned peers = __match_any_sync(amask, bin);
                if (lane == (__ffs(peers) - 1))
                    atomicAdd(&s_hist[bin], (uint32_t)__popc(peers));
            }
        }
        __syncthreads();

        // suffix sums over descending bins: s_scan[t] = sum_{b>=255-t} hist[b]
        if (tid < 256) {
            uint32_t v = s_hist[255 - tid];
            #pragma unroll
            for (int off = 1; off < 32; off <<= 1) {
                uint32_t u = __shfl_up_sync(0xffffffffu, v, off);
                if (lane >= off) v += u;
            }
            if (lane == 31) s_wtot[wid] = v;
            s_scan[tid] = v;
        }
        __syncthreads();
        if (tid < 256) {
            uint32_t add = 0;
            #pragma unroll
            for (int w = 0; w < 8; ++w) add += (wid > w) ? s_wtot[w] : 0u;
            s_scan[tid] += add;
        }
        __syncthreads();
        if (tid < 256) {
            int rem = s_rem;
            uint32_t inc = s_scan[tid];
            uint32_t prev = (tid == 0) ? 0u : s_scan[tid - 1];
            if ((int)inc >= rem && (int)prev < rem) {   // exactly one tid
                s_prefix = prefix | ((uint32_t)(255 - tid) << shift);
                s_rem = rem - (int)prev;
            }
        }
        __syncthreads();
    }

    const uint32_t T = s_prefix;   // exact K-th largest key
    const int      r = s_rem;      // # of ==T entries to keep (lowest index)

    // ---- marking: warp w owns keys [w*1024, (w+1)*1024), coalesced ----
    const int seg = wid << 10;

    // phase A: count ==T in this warp's segment
    int weq = 0;
    #pragma unroll 8
    for (int i = 0; i < 32; ++i) {
        uint32_t k = skeys[seg + i * 32 + lane];   // consecutive addrs/warp
        weq += __popc(__ballot_sync(0xffffffffu, k == T));
    }
    if (lane == 0) s_wtot[wid] = (uint32_t)weq;
    __syncthreads();

    // exclusive scan of the 32 warp totals (warp 0)
    if (wid == 0) {
        int v = (int)s_wtot[lane];
        #pragma unroll
        for (int off = 1; off < 32; off <<= 1) {
            int u = __shfl_up_sync(0xffffffffu, v, off);
            if (lane >= off) v += u;
        }
        s_wtot[lane] = (uint32_t)v;   // inclusive
    }
    __syncthreads();

    // phase B: mark with running index-ordered rank
    int rank = (wid == 0) ? 0 : (int)s_wtot[wid - 1];
    #pragma unroll 8
    for (int i = 0; i < 32; ++i) {
        int j = seg + i * 32 + lane;
        uint32_t k = skeys[j];
        bool eq = (k == T);
        unsigned ball = __ballot_sync(0xffffffffu, eq);
        int myrank = rank + __popc(ball & ((1u << lane) - 1u));
        out[j] = ((k > T) || (eq && myrank < r)) ? 1.0f : 0.0f;
        rank += __popc(ball);
    }
}

// ---------------------------------------------------------------------------
extern "C" void kernel_launch(void* const* d_in, const int* in_sizes, int n_in,
                              void* d_out, int out_size)
{
    const float* I    = (const float*)d_in[0];
    const float* perm = (const float*)d_in[1];
    const float* duty = (const float*)d_in[2];
    const float* navg = (const float*)d_in[3];
    float* out = (float*)d_out;

    (void)in_sizes; (void)n_in; (void)out_size;

    cudaFuncSetAttribute(topk_kernel,
                         cudaFuncAttributeMaxDynamicSharedMemorySize,
                         N_MC * (int)sizeof(uint32_t));

    overlap_kernel<<<N_MC / 32, 1024>>>(I, perm, duty, navg);
    topk_kernel<<<1, 1024, N_MC * sizeof(uint32_t)>>>(out);
}

// round 5
// speedup vs baseline: 1.1245x; 1.0092x over previous
#include <cuda_runtime.h>
#include <cuda_bf16.h>
#include <cstdint>
#include <math.h>

#define N_IN   8192
#define N_MC   32768
#define K_TOP  656
#define MASK_WORDS (N_IN / 32)          // 256

__device__ float g_overlap[N_MC];

// ---------------------------------------------------------------------------
// Kernel 1 (fused): per-block mask build + overlap
//   overlap_eff[row] = exp(na-dc) * popcount((perm_row >= 0.5) & I)
// 1024 threads/block, one warp per row (32 rows/block), float4 .cs streaming.
// Measured ~6.7 TB/s (84% of HBM spec) — at the practical roofline.
// ---------------------------------------------------------------------------
__global__ __launch_bounds__(1024) void overlap_kernel(
    const float* __restrict__ I,
    const float* __restrict__ perm,
    const float* __restrict__ duty,
    const float* __restrict__ navg)
{
    __shared__ uint32_t smask[MASK_WORDS];
    const int t    = threadIdx.x;
    const int warp = t >> 5;
    const int lane = t & 31;

    #pragma unroll
    for (int k2 = 0; k2 < 8; ++k2) {
        float v = I[k2 * 1024 + t];
        unsigned ball = __ballot_sync(0xffffffffu, v != 0.0f);
        if (lane == 0) smask[k2 * 32 + warp] = ball;
    }
    __syncthreads();

    const int row = blockIdx.x * 32 + warp;
    const float4* p = reinterpret_cast<const float4*>(perm + (size_t)row * N_IN);

    int cnt = 0;
    #pragma unroll 8
    for (int it = 0; it < 64; ++it) {
        int c4 = it * 32 + lane;
        float4 v = __ldcs(&p[c4]);
        int c = c4 * 4;
        uint32_t m = smask[c >> 5] >> (c & 31);
        cnt += ((m & 1u) && v.x >= 0.5f);
        cnt += ((m & 2u) && v.y >= 0.5f);
        cnt += ((m & 4u) && v.z >= 0.5f);
        cnt += ((m & 8u) && v.w >= 0.5f);
    }
    cnt = __reduce_add_sync(0xffffffffu, cnt);

    if (lane == 0) {
        float d = navg[row] - duty[row];
        float boost = (float)exp((double)d);     // correctly-rounded f32 exp
        g_overlap[row] = boost * (float)cnt;
    }
}

// ---------------------------------------------------------------------------
// Kernel 2: exact top-K (K=656), jax.lax.top_k tie semantics
// (threshold ties resolved lowest-index-first).
// Single block, 1024 threads. Keys held in REGISTERS (32/thread).
// 4 x 8-bit radix-select with PER-WARP histogram banks (no inter-warp
// atomic serialization), parallel suffix-scan bin pick, register marking.
// ---------------------------------------------------------------------------
__global__ __launch_bounds__(1024) void topk_kernel(float* __restrict__ out)
{
    __shared__ uint32_t s_hist[32][256];   // per-warp banks, 32 KB
    __shared__ uint32_t s_red[256];        // reduced histogram / scan
    __shared__ uint32_t s_wtot[32];
    __shared__ uint32_t s_prefix;
    __shared__ int      s_rem;

    const int tid  = threadIdx.x;
    const int lane = tid & 31;
    const int wid  = tid >> 5;
    const int seg  = wid << 10;            // warp's 1024-key segment

    // load this thread's 32 keys into registers (coalesced per warp;
    // all overlaps >= 0 so u32 bit order == float order)
    uint32_t key[32];
    #pragma unroll
    for (int i = 0; i < 32; ++i)
        key[i] = __float_as_uint(g_overlap[seg + i * 32 + lane]);

    if (tid == 0) { s_prefix = 0u; s_rem = K_TOP; }
    __syncthreads();

    // ---- radix select: find T = K-th largest key ----
    #pragma unroll
    for (int shift = 24; shift >= 0; shift -= 8) {
        // zero all banks: 32 KB / 1024 threads = 8 words each
        #pragma unroll
        for (int z = 0; z < 8; ++z)
            ((uint32_t*)s_hist)[z * 1024 + tid] = 0u;
        __syncthreads();
        const uint32_t prefix = s_prefix;

        #pragma unroll
        for (int i = 0; i < 32; ++i) {
            uint32_t k = key[i];
            bool cand = (shift == 24) || (((k ^ prefix) >> (shift + 8)) == 0u);
            unsigned amask = __ballot_sync(0xffffffffu, cand);
            if (cand) {
                uint32_t bin = (k >> shift) & 255u;
                unsigned peers = __match_any_sync(amask, bin);
                if (lane == (__ffs(peers) - 1))
                    atomicAdd(&s_hist[wid][bin], (uint32_t)__popc(peers));
            }
        }
        __syncthreads();

        // reduce 32 banks -> s_red[bin]  (conflict-free: fixed w, consecutive t)
        if (tid < 256) {
            uint32_t sum = 0;
            #pragma unroll
            for (int w = 0; w < 32; ++w) sum += s_hist[w][tid];
            s_red[tid] = sum;
        }
        __syncthreads();

        // suffix sums over descending bins: s_red'[t] = sum_{b>=255-t} red[b]
        if (tid < 256) {
            uint32_t v = s_red[255 - tid];
            #pragma unroll
            for (int off = 1; off < 32; off <<= 1) {
                uint32_t u = __shfl_up_sync(0xffffffffu, v, off);
                if (lane >= off) v += u;
            }
            if (lane == 31) s_wtot[wid] = v;
            s_hist[0][tid] = v;            // reuse bank 0 as scratch
        }
        __syncthreads();
        if (tid < 256) {
            uint32_t add = 0;
            #pragma unroll
            for (int w = 0; w < 8; ++w) add += (wid > w) ? s_wtot[w] : 0u;
            uint32_t inc = s_hist[0][tid] + add;
            int rem = s_rem;
            // need inclusive at tid and at tid-1; recompute prev inline
            s_hist[1][tid] = inc;          // bank 1 scratch: inclusive sums
            (void)rem;
        }
        __syncthreads();
        if (tid < 256) {
            int rem = s_rem;
            uint32_t inc  = s_hist[1][tid];
            uint32_t prev = (tid == 0) ? 0u : s_hist[1][tid - 1];
            if ((int)inc >= rem && (int)prev < rem) {   // exactly one tid
                s_prefix = prefix | ((uint32_t)(255 - tid) << shift);
                s_rem = rem - (int)prev;
            }
        }
        __syncthreads();
    }

    const uint32_t T = s_prefix;   // exact K-th largest key
    const int      r = s_rem;      // # of ==T entries to keep (lowest index)

    // ---- marking from registers: count, scan warp totals, mark ----
    int weq = 0;
    #pragma unroll
    for (int i = 0; i < 32; ++i)
        weq += __popc(__ballot_sync(0xffffffffu, key[i] == T));
    if (lane == 0) s_wtot[wid] = (uint32_t)weq;
    __syncthreads();

    if (wid == 0) {
        int v = (int)s_wtot[lane];
        #pragma unroll
        for (int off = 1; off < 32; off <<= 1) {
            int u = __shfl_up_sync(0xffffffffu, v, off);
            if (lane >= off) v += u;
        }
        s_wtot[lane] = (uint32_t)v;   // inclusive scan of warp totals
    }
    __syncthreads();

    int rank = (wid == 0) ? 0 : (int)s_wtot[wid - 1];
    #pragma unroll
    for (int i = 0; i < 32; ++i) {
        uint32_t k = key[i];
        bool eq = (k == T);
        unsigned ball = __ballot_sync(0xffffffffu, eq);
        int myrank = rank + __popc(ball & ((1u << lane) - 1u));
        out[seg + i * 32 + lane] = ((k > T) || (eq && myrank < r)) ? 1.0f : 0.0f;
        rank += __popc(ball);
    }
}

// ---------------------------------------------------------------------------
extern "C" void kernel_launch(void* const* d_in, const int* in_sizes, int n_in,
                              void* d_out, int out_size)
{
    const float* I    = (const float*)d_in[0];
    const float* perm = (const float*)d_in[1];
    const float* duty = (const float*)d_in[2];
    const float* navg = (const float*)d_in[3];
    float* out = (float*)d_out;

    (void)in_sizes; (void)n_in; (void)out_size;

    overlap_kernel<<<N_MC / 32, 1024>>>(I, perm, duty, navg);
    topk_kernel<<<1, 1024>>>(out);
}